// round 8
// baseline (speedup 1.0000x reference)
#include <cuda_runtime.h>
#include <cuda_bf16.h>
#include <math.h>
#include <stdint.h>

// Problem constants
#define NB 4
#define LV 2048
#define LE 64
#define LJ 2112        // LV + LE
#define DMODEL 960
#define NH 15
#define NKVH 5
#define HD 64
#define GQ 3           // NH / NKVH
#define QN (NH*HD)     // 960
#define KVN (NKVH*HD)  // 320
#define CEXP 0.18033688011112042f   // 0.125 * log2(e)

typedef __nv_bfloat16 bf16;

// Scratch (static device globals: allocation-free per harness rules)
__device__ bf16 g_xh_v[NB*LV*DMODEL];
__device__ bf16 g_xh_e[NB*LE*DMODEL];
__device__ bf16 g_qh[NB*LJ*QN];
__device__ bf16 g_kh[NB*LJ*KVN];
__device__ bf16 g_vt[NB*KVN*LJ];      // [b][kvh][d][l] transposed V
__device__ bf16 g_attn[NB*LJ*QN];
__device__ bf16 g_wh[4915200];        // bf16 transposed weights

// ---------------------------------------------------------------------------
// helpers
// ---------------------------------------------------------------------------
__device__ __forceinline__ uint32_t smem_u32(const void* p) {
  uint32_t a;
  asm("{ .reg .u64 t; cvta.to.shared.u64 t, %1; cvt.u32.u64 %0, t; }" : "=r"(a) : "l"(p));
  return a;
}
__device__ __forceinline__ float ex2(float x) {
  float y;
  asm("ex2.approx.ftz.f32 %0, %1;" : "=f"(y) : "f"(x));
  return y;
}
__device__ __forceinline__ void ldmx4(uint32_t r[4], uint32_t addr) {
  asm volatile("ldmatrix.sync.aligned.m8n8.x4.shared.b16 {%0,%1,%2,%3}, [%4];"
               : "=r"(r[0]), "=r"(r[1]), "=r"(r[2]), "=r"(r[3]) : "r"(addr));
}
__device__ __forceinline__ void cpa16(uint32_t dst, const void* src) {
  asm volatile("cp.async.cg.shared.global [%0], [%1], 16;" :: "r"(dst), "l"(src) : "memory");
}
#define CPA_COMMIT asm volatile("cp.async.commit_group;" ::: "memory")
#define CPA_WAIT2  asm volatile("cp.async.wait_group 2;" ::: "memory")

__device__ __forceinline__ uint32_t packbf(float x, float y) {
  __nv_bfloat162 h = __floats2bfloat162_rn(x, y);
  return *(uint32_t*)&h;
}

__device__ __forceinline__ void mma_bf16(float c[4], const uint32_t a[4],
                                         uint32_t b0, uint32_t b1) {
  asm volatile(
      "mma.sync.aligned.m16n8k16.row.col.f32.bf16.bf16.f32 "
      "{%0,%1,%2,%3}, {%4,%5,%6,%7}, {%8,%9}, {%0,%1,%2,%3};"
      : "+f"(c[0]), "+f"(c[1]), "+f"(c[2]), "+f"(c[3])
      : "r"(a[0]), "r"(a[1]), "r"(a[2]), "r"(a[3]), "r"(b0), "r"(b1));
}

// ---------------------------------------------------------------------------
// Fused weight transpose+convert: all 8 weights in one launch.
// ---------------------------------------------------------------------------
struct WP8 { const float* src[8]; };

__global__ void cvt_all(WP8 wp, bf16* __restrict__ dst) {
  const int SQc = 960 * 960, SKc = 960 * 320;
  const int Ns[8] = {960, 320, 320, 960, 960, 320, 320, 960};
  const int offs[8] = {0, SQc, SQc + SKc, SQc + 2 * SKc,
                       2 * SQc + 2 * SKc, 3 * SQc + 2 * SKc,
                       3 * SQc + 3 * SKc, 3 * SQc + 4 * SKc};
  int z = blockIdx.z;
  int N = Ns[z];
  int n0 = blockIdx.x * 32, k0 = blockIdx.y * 32;
  if (n0 >= N) return;
  const float* W = wp.src[z];
  bf16* Wt = dst + offs[z];
  __shared__ float t[32][33];
  int tx = threadIdx.x, ty = threadIdx.y;
  #pragma unroll
  for (int i = 0; i < 4; i++)
    t[ty + i * 8][tx] = W[(size_t)(k0 + ty + i * 8) * N + n0 + tx];
  __syncthreads();
  #pragma unroll
  for (int i = 0; i < 4; i++)
    Wt[(size_t)(n0 + ty + i * 8) * 960 + k0 + tx] = __float2bfloat16_rn(t[tx][ty + i * 8]);
}

// ---------------------------------------------------------------------------
// RMSNorm (bf16 output)
// ---------------------------------------------------------------------------
__global__ void rmsnorm_kernel(const float* __restrict__ x, const float* __restrict__ w,
                               bf16* __restrict__ out) {
  int row = blockIdx.x;
  const float* xr = x + (size_t)row * DMODEL;
  bf16* orow = out + (size_t)row * DMODEL;
  int t = threadIdx.x;
  float v[4];
  float ss = 0.f;
  #pragma unroll
  for (int i = 0; i < 4; i++) {
    int idx = t + i * 256;
    v[i] = (idx < DMODEL) ? xr[idx] : 0.f;
    ss += v[i] * v[i];
  }
  #pragma unroll
  for (int o = 16; o > 0; o >>= 1) ss += __shfl_xor_sync(0xffffffffu, ss, o);
  __shared__ float wsum[8];
  if ((t & 31) == 0) wsum[t >> 5] = ss;
  __syncthreads();
  if (t < 32) {
    float s = (t < 8) ? wsum[t] : 0.f;
    #pragma unroll
    for (int o = 4; o > 0; o >>= 1) s += __shfl_xor_sync(0xffffffffu, s, o);
    if (t == 0) wsum[0] = s;
  }
  __syncthreads();
  float rms = rsqrtf(wsum[0] * (1.f / DMODEL) + 1e-6f);
  #pragma unroll
  for (int i = 0; i < 4; i++) {
    int idx = t + i * 256;
    if (idx < DMODEL) orow[idx] = __float2bfloat16_rn(v[i] * rms * w[idx]);
  }
}

// ---------------------------------------------------------------------------
// bf16 mma GEMM. BM=256 BN=64 BK=64, 256 threads (8 warps 4x2, warp tile
// 64x32). 4-stage cp.async ring (wait_group 2); ldmatrix fragment loads.
// mode 0: bf16 out joint scatter; 1: fp32 out + resid; 2: transposed V out.
// ---------------------------------------------------------------------------
#define GBM 256
#define GPITCH 72
#define GABYTES (GBM*GPITCH*2)   // 36864
#define GBBYTES (64*GPITCH*2)    // 9216
#define GBUF (GABYTES+GBBYTES)   // 46080
#define GSTAGES 4
#define GEMM_SMEM (GSTAGES*GBUF) // 184320

__global__ void __launch_bounds__(256)
gemm_bf16(const bf16* __restrict__ A, const bf16* __restrict__ Wt,
          float* __restrict__ Cf, bf16* __restrict__ Cb,
          const float* __restrict__ resid,
          int N, int K, int Lsrc, int l_off, int a_joint, int mode) {
  extern __shared__ char sm[];
  uint32_t s0 = smem_u32(sm);
  int tid = threadIdx.x;
  int wid = tid >> 5, lane = tid & 31;
  int wm = wid >> 1, wn = wid & 1;
  int m0 = blockIdx.y * GBM, n0 = blockIdx.x * 64;

  const bf16* asrc[8]; uint32_t adst[8];
  #pragma unroll
  for (int i = 0; i < 8; i++) {
    int idx = tid + 256 * i;
    int row = idx >> 3, ch = idx & 7;
    int m = m0 + row;
    int grow = a_joint ? ((m / Lsrc) * LJ + l_off + (m % Lsrc)) : m;
    asrc[i] = A + (size_t)grow * K + ch * 8;
    adst[i] = row * (GPITCH * 2) + ch * 16;
  }
  const bf16* bsrc[2]; uint32_t bdst[2];
  #pragma unroll
  for (int i = 0; i < 2; i++) {
    int idx = tid + 256 * i;
    int row = idx >> 3, ch = idx & 7;
    bsrc[i] = Wt + (size_t)(n0 + row) * K + ch * 8;
    bdst[i] = GABYTES + row * (GPITCH * 2) + ch * 16;
  }

  float c[4][4][4];
  #pragma unroll
  for (int mt = 0; mt < 4; mt++)
    #pragma unroll
    for (int nt = 0; nt < 4; nt++)
      #pragma unroll
      for (int i = 0; i < 4; i++) c[mt][nt][i] = 0.f;

  uint32_t a_row = (uint32_t)(wm * 64 + (lane & 15)) * (GPITCH * 2) + ((lane >> 4) << 4);
  uint32_t b_row = (uint32_t)(wn * 32 + ((lane >> 4) << 3) + (lane & 7)) * (GPITCH * 2)
                   + (((lane >> 3) & 1) << 4);

  int nK = K >> 6;   // 15
  // prologue: tiles 0..2 -> stages 0..2 (one commit group per tile)
  #pragma unroll
  for (int p = 0; p < 3; p++) {
    uint32_t boff = p * GBUF;
    int k0 = p << 6;
    #pragma unroll
    for (int i = 0; i < 8; i++) cpa16(s0 + boff + adst[i], asrc[i] + k0);
    #pragma unroll
    for (int i = 0; i < 2; i++) cpa16(s0 + boff + bdst[i], bsrc[i] + k0);
    CPA_COMMIT;
  }

  for (int it = 0; it < nK; it++) {
    CPA_WAIT2;            // tile `it` complete (2 newer groups may be pending)
    __syncthreads();
    if (it + 3 < nK) {
      uint32_t boff = ((it + 3) & 3) * GBUF;
      int k0 = (it + 3) << 6;
      #pragma unroll
      for (int i = 0; i < 8; i++) cpa16(s0 + boff + adst[i], asrc[i] + k0);
      #pragma unroll
      for (int i = 0; i < 2; i++) cpa16(s0 + boff + bdst[i], bsrc[i] + k0);
    }
    CPA_COMMIT;           // one group per iteration (possibly empty at tail)

    uint32_t Ab = s0 + (it & 3) * GBUF;
    uint32_t Bb = Ab + GABYTES;
    #pragma unroll
    for (int kk = 0; kk < 4; kk++) {
      uint32_t a[4][4];
      #pragma unroll
      for (int mt = 0; mt < 4; mt++)
        ldmx4(a[mt], Ab + a_row + (uint32_t)(mt * 16) * (GPITCH * 2) + kk * 32);
      uint32_t bfr[2][4];
      #pragma unroll
      for (int j = 0; j < 2; j++)
        ldmx4(bfr[j], Bb + b_row + (uint32_t)(j * 16) * (GPITCH * 2) + kk * 32);
      #pragma unroll
      for (int j = 0; j < 2; j++)
        #pragma unroll
        for (int mt = 0; mt < 4; mt++) {
          mma_bf16(c[mt][2 * j],     a[mt], bfr[j][0], bfr[j][1]);
          mma_bf16(c[mt][2 * j + 1], a[mt], bfr[j][2], bfr[j][3]);
        }
    }
  }

  #pragma unroll
  for (int mt = 0; mt < 4; mt++) {
    #pragma unroll
    for (int hh = 0; hh < 2; hh++) {
      int m = m0 + wm * 64 + mt * 16 + (lane >> 2) + hh * 8;
      int bb = m / Lsrc, ll = m % Lsrc;
      int cr = bb * LJ + l_off + ll;
      #pragma unroll
      for (int nt = 0; nt < 4; nt++) {
        int cn = n0 + wn * 32 + nt * 8 + 2 * (lane & 3);
        float vx = c[mt][nt][2 * hh], vy = c[mt][nt][2 * hh + 1];
        if (mode == 0) {
          *(uint32_t*)(Cb + (size_t)cr * N + cn) = packbf(vx, vy);
        } else if (mode == 1) {
          float2 hv = *(const float2*)(resid + (size_t)m * N + cn);
          float2 o; o.x = vx + hv.x; o.y = vy + hv.y;
          *(float2*)(Cf + (size_t)cr * N + cn) = o;
        } else {
          int kvh = cn >> 6, d = cn & 63;
          size_t base = ((size_t)(bb * NKVH + kvh) * HD);
          Cb[(base + d) * LJ + l_off + ll] = __float2bfloat16_rn(vx);
          Cb[(base + d + 1) * LJ + l_off + ll] = __float2bfloat16_rn(vy);
        }
      }
    }
  }
}

// ---------------------------------------------------------------------------
// RoPE (in-place on bf16, fp32 math)
// ---------------------------------------------------------------------------
__global__ void rope_kernel(bf16* __restrict__ buf, int nh, int npairs,
                            const int* __restrict__ pv, const int* __restrict__ pe) {
  int pair = blockIdx.x * 8 + (threadIdx.x >> 5);
  if (pair >= npairs) return;
  int j = threadIdx.x & 31;
  int h = pair % nh;
  int r = pair / nh;
  int b = r / LJ;
  int l = r - b * LJ;
  int pos = (l < LV) ? pv[b * LV + l] : pe[b * LE + (l - LV)];
  float dinv = exp2f((float)j * -0.41524101186092016f);  // 10000^(-j/32)
  float rad = (float)pos * dinv;
  float sn, cs;
  sincosf(rad, &sn, &cs);
  bf16* p = buf + (size_t)r * (nh * HD) + h * HD;
  float x1 = __bfloat162float(p[j]);
  float x2 = __bfloat162float(p[j + 32]);
  p[j] = __float2bfloat16_rn(x1 * cs - x2 * sn);
  p[j + 32] = __float2bfloat16_rn(x2 * cs + x1 * sn);
}

// ---------------------------------------------------------------------------
// Flash attention, bf16 mma + ldmatrix. Block = 128 threads (4 warps),
// 128 q rows per (head h, batch b): warp owns 32 rows (two m16 groups).
// 4-stage 64-key KV ring (wait_group 2), V pre-transposed [d][l].
// P stays in registers.
// ---------------------------------------------------------------------------
#define APITCH 72
#define ATBYTES (64*APITCH*2)     // 9216
#define AQBYTES (128*APITCH*2)    // 18432
#define ASTAGE (2*ATBYTES)        // 18432 (K + V)
#define AKOFF(st) (AQBYTES + (st)*ASTAGE)
#define AVOFF(st) (AQBYTES + (st)*ASTAGE + ATBYTES)
#define ATTN_SMEM (AQBYTES + 4*ASTAGE)   // 92160

__global__ void __launch_bounds__(128)
attn_mma(const bf16* __restrict__ Qg, const bf16* __restrict__ Kg,
         const bf16* __restrict__ Vt, bf16* __restrict__ Og) {
  extern __shared__ char sm[];
  uint32_t s0 = smem_u32(sm);
  int tid = threadIdx.x;
  int wid = tid >> 5, lane = tid & 31;
  int h = blockIdx.y, b = blockIdx.z;
  int kvh = h / GQ;
  int q0 = blockIdx.x * 128;
  int nT = (q0 < LV) ? (LV / 64) : (LJ / 64);  // 32 or 33

  int qrow[8], qch[8];
  #pragma unroll
  for (int i = 0; i < 8; i++) {
    int idx = tid + 128 * i;
    qrow[i] = idx >> 3;
    qch[i] = idx & 7;
  }
  int crow[4], cch[4];
  #pragma unroll
  for (int i = 0; i < 4; i++) {
    int idx = tid + 128 * i;
    crow[i] = idx >> 3;
    cch[i] = idx & 7;
  }
  const bf16* vbase = Vt + (size_t)(b * NKVH + kvh) * HD * LJ;

  // prologue: group0 = Q + KV tile 0; groups 1,2 = KV tiles 1,2
  #pragma unroll
  for (int i = 0; i < 8; i++) {
    int gr = q0 + qrow[i];
    if (gr > LJ - 1) gr = LJ - 1;
    const bf16* src = Qg + ((size_t)(b * LJ + gr)) * QN + h * HD + qch[i] * 8;
    cpa16(s0 + qrow[i] * (APITCH * 2) + qch[i] * 16, src);
  }
  #pragma unroll
  for (int p = 0; p < 3; p++) {
    int kr0 = p * 64;
    #pragma unroll
    for (int i = 0; i < 4; i++) {
      const bf16* ks = Kg + ((size_t)(b * LJ + kr0 + crow[i])) * KVN + kvh * HD + cch[i] * 8;
      const bf16* vs = vbase + (size_t)crow[i] * LJ + kr0 + cch[i] * 8;
      cpa16(s0 + AKOFF(p) + crow[i] * (APITCH * 2) + cch[i] * 16, ks);
      cpa16(s0 + AVOFF(p) + crow[i] * (APITCH * 2) + cch[i] * 16, vs);
    }
    CPA_COMMIT;
  }

  float o[2][8][4];
  #pragma unroll
  for (int g = 0; g < 2; g++)
    #pragma unroll
    for (int nt = 0; nt < 8; nt++)
      #pragma unroll
      for (int i = 0; i < 4; i++) o[g][nt][i] = 0.f;
  float mi[2][2], li[2][2];
  #pragma unroll
  for (int g = 0; g < 2; g++) { mi[g][0] = mi[g][1] = -1e30f; li[g][0] = li[g][1] = 0.f; }

  uint32_t qf[2][4][4];
  int r0 = lane >> 2;
  int kc0 = 2 * (lane & 3);
  uint32_t q_ldm = (uint32_t)(wid * 32 + (lane & 15)) * (APITCH * 2) + ((lane >> 4) << 4);
  uint32_t kv_ldm = (uint32_t)(((lane >> 4) << 3) + (lane & 7)) * (APITCH * 2)
                    + (((lane >> 3) & 1) << 4);

  for (int it = 0; it < nT; it++) {
    CPA_WAIT2;
    __syncthreads();
    if (it + 3 < nT) {
      int st = (it + 3) & 3;
      int kr0 = (it + 3) * 64;
      #pragma unroll
      for (int i = 0; i < 4; i++) {
        const bf16* ks = Kg + ((size_t)(b * LJ + kr0 + crow[i])) * KVN + kvh * HD + cch[i] * 8;
        const bf16* vs = vbase + (size_t)crow[i] * LJ + kr0 + cch[i] * 8;
        cpa16(s0 + AKOFF(st) + crow[i] * (APITCH * 2) + cch[i] * 16, ks);
        cpa16(s0 + AVOFF(st) + crow[i] * (APITCH * 2) + cch[i] * 16, vs);
      }
    }
    CPA_COMMIT;

    if (it == 0) {
      #pragma unroll
      for (int g = 0; g < 2; g++)
        #pragma unroll
        for (int kk = 0; kk < 4; kk++)
          ldmx4(qf[g][kk], s0 + q_ldm + (uint32_t)(g * 16) * (APITCH * 2) + kk * 32);
    }

    // ---- S = Q K^T ----
    uint32_t Kb = s0 + AKOFF(it & 3);
    float s[2][8][4];
    #pragma unroll
    for (int g = 0; g < 2; g++)
      #pragma unroll
      for (int nt = 0; nt < 8; nt++)
        s[g][nt][0] = s[g][nt][1] = s[g][nt][2] = s[g][nt][3] = 0.f;
    #pragma unroll
    for (int kk = 0; kk < 4; kk++) {
      uint32_t kb4[4][4];
      #pragma unroll
      for (int j = 0; j < 4; j++)
        ldmx4(kb4[j], Kb + kv_ldm + (uint32_t)(j * 16) * (APITCH * 2) + kk * 32);
      #pragma unroll
      for (int j = 0; j < 4; j++) {
        mma_bf16(s[0][2 * j],     qf[0][kk], kb4[j][0], kb4[j][1]);
        mma_bf16(s[1][2 * j],     qf[1][kk], kb4[j][0], kb4[j][1]);
        mma_bf16(s[0][2 * j + 1], qf[0][kk], kb4[j][2], kb4[j][3]);
        mma_bf16(s[1][2 * j + 1], qf[1][kk], kb4[j][2], kb4[j][3]);
      }
    }

    // causal mask (expert q-block, last KV tile only)
    if (q0 >= LV && it == nT - 1) {
      int tk = it * 64;
      #pragma unroll
      for (int g = 0; g < 2; g++) {
        int rl = q0 + wid * 32 + g * 16 + r0;
        #pragma unroll
        for (int nt = 0; nt < 8; nt++) {
          int key = tk + nt * 8 + kc0;
          if (key > rl)         s[g][nt][0] = -1e30f;
          if (key + 1 > rl)     s[g][nt][1] = -1e30f;
          if (key > rl + 8)     s[g][nt][2] = -1e30f;
          if (key + 1 > rl + 8) s[g][nt][3] = -1e30f;
        }
      }
    }

    // ---- online softmax (per row group); p overwrites s ----
    #pragma unroll
    for (int g = 0; g < 2; g++) {
      float tm0 = -1e30f, tm1 = -1e30f;
      #pragma unroll
      for (int nt = 0; nt < 8; nt++) {
        tm0 = fmaxf(tm0, fmaxf(s[g][nt][0], s[g][nt][1]));
        tm1 = fmaxf(tm1, fmaxf(s[g][nt][2], s[g][nt][3]));
      }
      tm0 = fmaxf(tm0, __shfl_xor_sync(0xffffffffu, tm0, 1));
      tm0 = fmaxf(tm0, __shfl_xor_sync(0xffffffffu, tm0, 2));
      tm1 = fmaxf(tm1, __shfl_xor_sync(0xffffffffu, tm1, 1));
      tm1 = fmaxf(tm1, __shfl_xor_sync(0xffffffffu, tm1, 2));
      float mn0 = fmaxf(mi[g][0], tm0), mn1 = fmaxf(mi[g][1], tm1);
      float cr0 = ex2((mi[g][0] - mn0) * CEXP), cr1 = ex2((mi[g][1] - mn1) * CEXP);
      li[g][0] *= cr0; li[g][1] *= cr1;
      #pragma unroll
      for (int nt = 0; nt < 8; nt++) {
        o[g][nt][0] *= cr0; o[g][nt][1] *= cr0;
        o[g][nt][2] *= cr1; o[g][nt][3] *= cr1;
      }
      #pragma unroll
      for (int nt = 0; nt < 8; nt++) {
        float p0 = ex2((s[g][nt][0] - mn0) * CEXP);
        float p1 = ex2((s[g][nt][1] - mn0) * CEXP);
        float p2 = ex2((s[g][nt][2] - mn1) * CEXP);
        float p3 = ex2((s[g][nt][3] - mn1) * CEXP);
        li[g][0] += p0 + p1;
        li[g][1] += p2 + p3;
        s[g][nt][0] = p0; s[g][nt][1] = p1; s[g][nt][2] = p2; s[g][nt][3] = p3;
      }
      mi[g][0] = mn0; mi[g][1] = mn1;
    }

    // ---- O += P V (P direct from registers; V fragments shared) ----
    uint32_t Vb = s0 + AVOFF(it & 3);
    #pragma unroll
    for (int kk = 0; kk < 4; kk++) {
      uint32_t a[2][4];
      #pragma unroll
      for (int g = 0; g < 2; g++) {
        a[g][0] = packbf(s[g][2 * kk][0], s[g][2 * kk][1]);
        a[g][1] = packbf(s[g][2 * kk][2], s[g][2 * kk][3]);
        a[g][2] = packbf(s[g][2 * kk + 1][0], s[g][2 * kk + 1][1]);
        a[g][3] = packbf(s[g][2 * kk + 1][2], s[g][2 * kk + 1][3]);
      }
      uint32_t vb4[4][4];
      #pragma unroll
      for (int j = 0; j < 4; j++)
        ldmx4(vb4[j], Vb + kv_ldm + (uint32_t)(j * 16) * (APITCH * 2) + kk * 32);
      #pragma unroll
      for (int j = 0; j < 4; j++) {
        mma_bf16(o[0][2 * j],     a[0], vb4[j][0], vb4[j][1]);
        mma_bf16(o[1][2 * j],     a[1], vb4[j][0], vb4[j][1]);
        mma_bf16(o[0][2 * j + 1], a[0], vb4[j][2], vb4[j][3]);
        mma_bf16(o[1][2 * j + 1], a[1], vb4[j][2], vb4[j][3]);
      }
    }
  }

  // finalize
  #pragma unroll
  for (int g = 0; g < 2; g++) {
    if (q0 + wid * 32 + g * 16 >= LJ) continue;
    float l0 = li[g][0], l1 = li[g][1];
    l0 += __shfl_xor_sync(0xffffffffu, l0, 1);
    l0 += __shfl_xor_sync(0xffffffffu, l0, 2);
    l1 += __shfl_xor_sync(0xffffffffu, l1, 1);
    l1 += __shfl_xor_sync(0xffffffffu, l1, 2);
    float inv0 = 1.f / l0, inv1 = 1.f / l1;
    int gr0 = b * LJ + q0 + wid * 32 + g * 16 + r0;
    #pragma unroll
    for (int nt = 0; nt < 8; nt++) {
      int cn = h * HD + nt * 8 + kc0;
      *(uint32_t*)(Og + (size_t)gr0 * QN + cn) = packbf(o[g][nt][0] * inv0, o[g][nt][1] * inv0);
      *(uint32_t*)(Og + (size_t)(gr0 + 8) * QN + cn) = packbf(o[g][nt][2] * inv1, o[g][nt][3] * inv1);
    }
  }
}

// ---------------------------------------------------------------------------
// Launch
// ---------------------------------------------------------------------------
extern "C" void kernel_launch(void* const* d_in, const int* in_sizes, int n_in,
                              void* d_out, int out_size) {
  const float* hv  = (const float*)d_in[0];
  const float* he  = (const float*)d_in[1];
  const float* lnv = (const float*)d_in[2];
  const float* wqv = (const float*)d_in[3];
  const float* wkv = (const float*)d_in[4];
  const float* wvv = (const float*)d_in[5];
  const float* wov = (const float*)d_in[6];
  const float* lne = (const float*)d_in[7];
  const float* wqe = (const float*)d_in[8];
  const float* wke = (const float*)d_in[9];
  const float* wve = (const float*)d_in[10];
  const float* woe = (const float*)d_in[11];
  const int* pv = (const int*)d_in[12];
  const int* pe = (const int*)d_in[13];
  float* out = (float*)d_out;

  bf16 *xhv, *xhe, *qh, *kh, *vt, *attn, *wh;
  cudaGetSymbolAddress((void**)&xhv, g_xh_v);
  cudaGetSymbolAddress((void**)&xhe, g_xh_e);
  cudaGetSymbolAddress((void**)&qh,  g_qh);
  cudaGetSymbolAddress((void**)&kh,  g_kh);
  cudaGetSymbolAddress((void**)&vt,  g_vt);
  cudaGetSymbolAddress((void**)&attn, g_attn);
  cudaGetSymbolAddress((void**)&wh,  g_wh);

  cudaFuncSetAttribute(gemm_bf16, cudaFuncAttributeMaxDynamicSharedMemorySize, GEMM_SMEM);
  cudaFuncSetAttribute(attn_mma, cudaFuncAttributeMaxDynamicSharedMemorySize, ATTN_SMEM);

  const int SQ = 960 * 960, SK = 960 * 320;
  bf16* cwqv = wh;
  bf16* cwkv = wh + SQ;
  bf16* cwvv = wh + SQ + SK;
  bf16* cwov = wh + SQ + 2 * SK;
  bf16* cwqe = wh + 2 * SQ + 2 * SK;
  bf16* cwke = wh + 3 * SQ + 2 * SK;
  bf16* cwve = wh + 3 * SQ + 3 * SK;
  bf16* cwoe = wh + 3 * SQ + 4 * SK;

  // 0) Fused weight transpose+convert (1 launch)
  WP8 wp;
  wp.src[0] = wqv; wp.src[1] = wkv; wp.src[2] = wvv; wp.src[3] = wov;
  wp.src[4] = wqe; wp.src[5] = wke; wp.src[6] = wve; wp.src[7] = woe;
  cvt_all<<<dim3(30, 30, 8), dim3(32, 8)>>>(wp, wh);

  // 1) RMSNorm (bf16 outputs)
  rmsnorm_kernel<<<NB * LV, 256>>>(hv, lnv, xhv);
  rmsnorm_kernel<<<NB * LE, 256>>>(he, lne, xhe);

  // 2) QKV projections
  gemm_bf16<<<dim3(QN / 64, 32), 256, GEMM_SMEM>>>(xhv, cwqv, nullptr, qh, nullptr, QN,  DMODEL, LV, 0,  0, 0);
  gemm_bf16<<<dim3(KVN / 64, 32), 256, GEMM_SMEM>>>(xhv, cwkv, nullptr, kh, nullptr, KVN, DMODEL, LV, 0,  0, 0);
  gemm_bf16<<<dim3(KVN / 64, 32), 256, GEMM_SMEM>>>(xhv, cwvv, nullptr, vt, nullptr, KVN, DMODEL, LV, 0,  0, 2);
  gemm_bf16<<<dim3(QN / 64, 1), 256, GEMM_SMEM>>>(xhe, cwqe, nullptr, qh, nullptr, QN,  DMODEL, LE, LV, 0, 0);
  gemm_bf16<<<dim3(KVN / 64, 1), 256, GEMM_SMEM>>>(xhe, cwke, nullptr, kh, nullptr, KVN, DMODEL, LE, LV, 0, 0);
  gemm_bf16<<<dim3(KVN / 64, 1), 256, GEMM_SMEM>>>(xhe, cwve, nullptr, vt, nullptr, KVN, DMODEL, LE, LV, 0, 2);

  // 3) RoPE on q and k (in place, bf16, fp32 math)
  int pq = NB * LJ * NH;
  int pk = NB * LJ * NKVH;
  rope_kernel<<<(pq + 7) / 8, 256>>>(qh, NH,   pq, pv, pe);
  rope_kernel<<<(pk + 7) / 8, 256>>>(kh, NKVH, pk, pv, pe);

  // 4) Attention (128 q rows per block)
  attn_mma<<<dim3((LJ + 127) / 128, NH, NB), 128, ATTN_SMEM>>>(qh, kh, vt, attn);

  // 5) Output projection + residual
  gemm_bf16<<<dim3(QN / 64, 32), 256, GEMM_SMEM>>>(attn, cwov, out, nullptr, hv, QN, DMODEL, LV, 0,  1, 1);
  gemm_bf16<<<dim3(QN / 64, 1), 256, GEMM_SMEM>>>(attn, cwoe, out, nullptr, he, QN, DMODEL, LE, LV, 1, 1);
}

// round 10
// speedup vs baseline: 1.0163x; 1.0163x over previous
#include <cuda_runtime.h>
#include <cuda_bf16.h>
#include <math.h>
#include <stdint.h>

// Problem constants
#define NB 4
#define LV 2048
#define LE 64
#define LJ 2112        // LV + LE
#define DMODEL 960
#define NH 15
#define NKVH 5
#define HD 64
#define GQ 3           // NH / NKVH
#define QN (NH*HD)     // 960
#define KVN (NKVH*HD)  // 320
#define CEXP 0.18033688011112042f   // 0.125 * log2(e)

typedef __nv_bfloat16 bf16;

// Scratch (static device globals: allocation-free per harness rules)
__device__ bf16 g_xh_v[NB*LV*DMODEL];
__device__ bf16 g_xh_e[NB*LE*DMODEL];
__device__ bf16 g_qh[NB*LJ*QN];
__device__ bf16 g_kh[NB*LJ*KVN];
__device__ bf16 g_vt[NB*KVN*LJ];      // [b][kvh][d][l] transposed V
__device__ bf16 g_attn[NB*LJ*QN];
__device__ bf16 g_wh[4915200];        // bf16 transposed weights

// ---------------------------------------------------------------------------
// helpers
// ---------------------------------------------------------------------------
__device__ __forceinline__ uint32_t smem_u32(const void* p) {
  uint32_t a;
  asm("{ .reg .u64 t; cvta.to.shared.u64 t, %1; cvt.u32.u64 %0, t; }" : "=r"(a) : "l"(p));
  return a;
}
__device__ __forceinline__ float ex2(float x) {
  float y;
  asm("ex2.approx.ftz.f32 %0, %1;" : "=f"(y) : "f"(x));
  return y;
}
__device__ __forceinline__ void ldmx4(uint32_t r[4], uint32_t addr) {
  asm volatile("ldmatrix.sync.aligned.m8n8.x4.shared.b16 {%0,%1,%2,%3}, [%4];"
               : "=r"(r[0]), "=r"(r[1]), "=r"(r[2]), "=r"(r[3]) : "r"(addr));
}
__device__ __forceinline__ void cpa16(uint32_t dst, const void* src) {
  asm volatile("cp.async.cg.shared.global [%0], [%1], 16;" :: "r"(dst), "l"(src) : "memory");
}
#define CPA_COMMIT asm volatile("cp.async.commit_group;" ::: "memory")
#define CPA_WAIT2  asm volatile("cp.async.wait_group 2;" ::: "memory")

__device__ __forceinline__ uint32_t packbf(float x, float y) {
  __nv_bfloat162 h = __floats2bfloat162_rn(x, y);
  return *(uint32_t*)&h;
}

__device__ __forceinline__ void mma_bf16(float c[4], const uint32_t a[4],
                                         uint32_t b0, uint32_t b1) {
  asm volatile(
      "mma.sync.aligned.m16n8k16.row.col.f32.bf16.bf16.f32 "
      "{%0,%1,%2,%3}, {%4,%5,%6,%7}, {%8,%9}, {%0,%1,%2,%3};"
      : "+f"(c[0]), "+f"(c[1]), "+f"(c[2]), "+f"(c[3])
      : "r"(a[0]), "r"(a[1]), "r"(a[2]), "r"(a[3]), "r"(b0), "r"(b1));
}

// ---------------------------------------------------------------------------
// Fused weight transpose+convert: all 8 weights in one launch.
// ---------------------------------------------------------------------------
struct WP8 { const float* src[8]; };

__global__ void cvt_all(WP8 wp, bf16* __restrict__ dst) {
  const int SQc = 960 * 960, SKc = 960 * 320;
  const int Ns[8] = {960, 320, 320, 960, 960, 320, 320, 960};
  const int offs[8] = {0, SQc, SQc + SKc, SQc + 2 * SKc,
                       2 * SQc + 2 * SKc, 3 * SQc + 2 * SKc,
                       3 * SQc + 3 * SKc, 3 * SQc + 4 * SKc};
  int z = blockIdx.z;
  int N = Ns[z];
  int n0 = blockIdx.x * 32, k0 = blockIdx.y * 32;
  if (n0 >= N) return;
  const float* W = wp.src[z];
  bf16* Wt = dst + offs[z];
  __shared__ float t[32][33];
  int tx = threadIdx.x, ty = threadIdx.y;
  #pragma unroll
  for (int i = 0; i < 4; i++)
    t[ty + i * 8][tx] = W[(size_t)(k0 + ty + i * 8) * N + n0 + tx];
  __syncthreads();
  #pragma unroll
  for (int i = 0; i < 4; i++)
    Wt[(size_t)(n0 + ty + i * 8) * 960 + k0 + tx] = __float2bfloat16_rn(t[tx][ty + i * 8]);
}

// ---------------------------------------------------------------------------
// RMSNorm (bf16 output)
// ---------------------------------------------------------------------------
__global__ void rmsnorm_kernel(const float* __restrict__ x, const float* __restrict__ w,
                               bf16* __restrict__ out) {
  int row = blockIdx.x;
  const float* xr = x + (size_t)row * DMODEL;
  bf16* orow = out + (size_t)row * DMODEL;
  int t = threadIdx.x;
  float v[4];
  float ss = 0.f;
  #pragma unroll
  for (int i = 0; i < 4; i++) {
    int idx = t + i * 256;
    v[i] = (idx < DMODEL) ? xr[idx] : 0.f;
    ss += v[i] * v[i];
  }
  #pragma unroll
  for (int o = 16; o > 0; o >>= 1) ss += __shfl_xor_sync(0xffffffffu, ss, o);
  __shared__ float wsum[8];
  if ((t & 31) == 0) wsum[t >> 5] = ss;
  __syncthreads();
  if (t < 32) {
    float s = (t < 8) ? wsum[t] : 0.f;
    #pragma unroll
    for (int o = 4; o > 0; o >>= 1) s += __shfl_xor_sync(0xffffffffu, s, o);
    if (t == 0) wsum[0] = s;
  }
  __syncthreads();
  float rms = rsqrtf(wsum[0] * (1.f / DMODEL) + 1e-6f);
  #pragma unroll
  for (int i = 0; i < 4; i++) {
    int idx = t + i * 256;
    if (idx < DMODEL) orow[idx] = __float2bfloat16_rn(v[i] * rms * w[idx]);
  }
}

// ---------------------------------------------------------------------------
// bf16 mma GEMM. BM=256 BN=64 BK=64, 512 threads (16 warps 8x2, warp tile
// 32x32 -> 4 warps/SMSP). 4-stage cp.async ring; ldmatrix fragment loads.
// mode 0: bf16 out joint scatter; 1: fp32 out + resid; 2: transposed V out.
// ---------------------------------------------------------------------------
#define GBM 256
#define GPITCH 72
#define GABYTES (GBM*GPITCH*2)   // 36864
#define GBBYTES (64*GPITCH*2)    // 9216
#define GBUF (GABYTES+GBBYTES)   // 46080
#define GSTAGES 4
#define GEMM_SMEM (GSTAGES*GBUF) // 184320

__global__ void __launch_bounds__(512)
gemm_bf16(const bf16* __restrict__ A, const bf16* __restrict__ Wt,
          float* __restrict__ Cf, bf16* __restrict__ Cb,
          const float* __restrict__ resid,
          int N, int K, int Lsrc, int l_off, int a_joint, int mode) {
  extern __shared__ char sm[];
  uint32_t s0 = smem_u32(sm);
  int tid = threadIdx.x;
  int wid = tid >> 5, lane = tid & 31;
  int wm = wid >> 1, wn = wid & 1;           // wm 0..7 (32 rows), wn 0..1 (32 cols)
  int m0 = blockIdx.y * GBM, n0 = blockIdx.x * 64;

  // loaders: A 4 chunks/thread, B 1 chunk/thread
  const bf16* asrc[4]; uint32_t adst[4];
  #pragma unroll
  for (int i = 0; i < 4; i++) {
    int idx = tid + 512 * i;
    int row = idx >> 3, ch = idx & 7;
    int m = m0 + row;
    int grow = a_joint ? ((m / Lsrc) * LJ + l_off + (m % Lsrc)) : m;
    asrc[i] = A + (size_t)grow * K + ch * 8;
    adst[i] = row * (GPITCH * 2) + ch * 16;
  }
  const bf16* bsrc = Wt + (size_t)(n0 + (tid >> 3)) * K + (tid & 7) * 8;
  uint32_t bdst = GABYTES + (tid >> 3) * (GPITCH * 2) + (tid & 7) * 16;

  float c[2][4][4];
  #pragma unroll
  for (int mt = 0; mt < 2; mt++)
    #pragma unroll
    for (int nt = 0; nt < 4; nt++)
      #pragma unroll
      for (int i = 0; i < 4; i++) c[mt][nt][i] = 0.f;

  uint32_t a_row = (uint32_t)(wm * 32 + (lane & 15)) * (GPITCH * 2) + ((lane >> 4) << 4);
  uint32_t b_row = (uint32_t)(wn * 32 + ((lane >> 4) << 3) + (lane & 7)) * (GPITCH * 2)
                   + (((lane >> 3) & 1) << 4);

  int nK = K >> 6;   // 15
  #pragma unroll
  for (int p = 0; p < 3; p++) {
    uint32_t boff = p * GBUF;
    int k0 = p << 6;
    #pragma unroll
    for (int i = 0; i < 4; i++) cpa16(s0 + boff + adst[i], asrc[i] + k0);
    cpa16(s0 + boff + bdst, bsrc + k0);
    CPA_COMMIT;
  }

  for (int it = 0; it < nK; it++) {
    CPA_WAIT2;
    __syncthreads();
    if (it + 3 < nK) {
      uint32_t boff = ((it + 3) & 3) * GBUF;
      int k0 = (it + 3) << 6;
      #pragma unroll
      for (int i = 0; i < 4; i++) cpa16(s0 + boff + adst[i], asrc[i] + k0);
      cpa16(s0 + boff + bdst, bsrc + k0);
    }
    CPA_COMMIT;

    uint32_t Ab = s0 + (it & 3) * GBUF;
    uint32_t Bb = Ab + GABYTES;
    #pragma unroll
    for (int kk = 0; kk < 4; kk++) {
      uint32_t a[2][4];
      #pragma unroll
      for (int mt = 0; mt < 2; mt++)
        ldmx4(a[mt], Ab + a_row + (uint32_t)(mt * 16) * (GPITCH * 2) + kk * 32);
      uint32_t bfr[2][4];
      #pragma unroll
      for (int j = 0; j < 2; j++)
        ldmx4(bfr[j], Bb + b_row + (uint32_t)(j * 16) * (GPITCH * 2) + kk * 32);
      #pragma unroll
      for (int j = 0; j < 2; j++)
        #pragma unroll
        for (int mt = 0; mt < 2; mt++) {
          mma_bf16(c[mt][2 * j],     a[mt], bfr[j][0], bfr[j][1]);
          mma_bf16(c[mt][2 * j + 1], a[mt], bfr[j][2], bfr[j][3]);
        }
    }
  }

  #pragma unroll
  for (int mt = 0; mt < 2; mt++) {
    #pragma unroll
    for (int hh = 0; hh < 2; hh++) {
      int m = m0 + wm * 32 + mt * 16 + (lane >> 2) + hh * 8;
      int bb = m / Lsrc, ll = m % Lsrc;
      int cr = bb * LJ + l_off + ll;
      #pragma unroll
      for (int nt = 0; nt < 4; nt++) {
        int cn = n0 + wn * 32 + nt * 8 + 2 * (lane & 3);
        float vx = c[mt][nt][2 * hh], vy = c[mt][nt][2 * hh + 1];
        if (mode == 0) {
          *(uint32_t*)(Cb + (size_t)cr * N + cn) = packbf(vx, vy);
        } else if (mode == 1) {
          float2 hv = *(const float2*)(resid + (size_t)m * N + cn);
          float2 o; o.x = vx + hv.x; o.y = vy + hv.y;
          *(float2*)(Cf + (size_t)cr * N + cn) = o;
        } else {
          int kvh = cn >> 6, d = cn & 63;
          size_t base = ((size_t)(bb * NKVH + kvh) * HD);
          Cb[(base + d) * LJ + l_off + ll] = __float2bfloat16_rn(vx);
          Cb[(base + d + 1) * LJ + l_off + ll] = __float2bfloat16_rn(vy);
        }
      }
    }
  }
}

// ---------------------------------------------------------------------------
// RoPE (in-place on bf16, fp32 math)
// ---------------------------------------------------------------------------
__global__ void rope_kernel(bf16* __restrict__ buf, int nh, int npairs,
                            const int* __restrict__ pv, const int* __restrict__ pe) {
  int pair = blockIdx.x * 8 + (threadIdx.x >> 5);
  if (pair >= npairs) return;
  int j = threadIdx.x & 31;
  int h = pair % nh;
  int r = pair / nh;
  int b = r / LJ;
  int l = r - b * LJ;
  int pos = (l < LV) ? pv[b * LV + l] : pe[b * LE + (l - LV)];
  float dinv = exp2f((float)j * -0.41524101186092016f);  // 10000^(-j/32)
  float rad = (float)pos * dinv;
  float sn, cs;
  sincosf(rad, &sn, &cs);
  bf16* p = buf + (size_t)r * (nh * HD) + h * HD;
  float x1 = __bfloat162float(p[j]);
  float x2 = __bfloat162float(p[j + 32]);
  p[j] = __float2bfloat16_rn(x1 * cs - x2 * sn);
  p[j + 32] = __float2bfloat16_rn(x2 * cs + x1 * sn);
}

// ---------------------------------------------------------------------------
// Flash attention, bf16 mma + ldmatrix. Block = 256 threads (8 warps),
// 128 q rows per (head h, batch b): warp owns 16 rows. Forced 2 CTAs/SM
// (__launch_bounds__(256,2)) -> 16 warps/SM = 4/SMSP.
// 4-stage 64-key KV ring, V pre-transposed [d][l]. P stays in registers.
// ---------------------------------------------------------------------------
#define APITCH 72
#define ATBYTES (64*APITCH*2)     // 9216
#define AQBYTES (128*APITCH*2)    // 18432
#define ASTAGE (2*ATBYTES)        // 18432 (K + V)
#define AKOFF(st) (AQBYTES + (st)*ASTAGE)
#define AVOFF(st) (AQBYTES + (st)*ASTAGE + ATBYTES)
#define ATTN_SMEM (AQBYTES + 4*ASTAGE)   // 92160

__global__ void __launch_bounds__(256, 2)
attn_mma(const bf16* __restrict__ Qg, const bf16* __restrict__ Kg,
         const bf16* __restrict__ Vt, bf16* __restrict__ Og) {
  extern __shared__ char sm[];
  uint32_t s0 = smem_u32(sm);
  int tid = threadIdx.x;
  int wid = tid >> 5, lane = tid & 31;
  int h = blockIdx.y, b = blockIdx.z;
  int kvh = h / GQ;
  int q0 = blockIdx.x * 128;
  int nT = (q0 < LV) ? (LV / 64) : (LJ / 64);  // 32 or 33

  // cp.async chunk mappings (256 threads)
  int qrow[4], qch[4];
  #pragma unroll
  for (int i = 0; i < 4; i++) {
    int idx = tid + 256 * i;
    qrow[i] = idx >> 3;
    qch[i] = idx & 7;
  }
  int crow[2], cch[2];
  #pragma unroll
  for (int i = 0; i < 2; i++) {
    int idx = tid + 256 * i;
    crow[i] = idx >> 3;
    cch[i] = idx & 7;
  }
  const bf16* vbase = Vt + (size_t)(b * NKVH + kvh) * HD * LJ;

  // prologue: group0 = Q + KV tile 0; groups 1,2 = KV tiles 1,2
  #pragma unroll
  for (int i = 0; i < 4; i++) {
    int gr = q0 + qrow[i];
    if (gr > LJ - 1) gr = LJ - 1;
    const bf16* src = Qg + ((size_t)(b * LJ + gr)) * QN + h * HD + qch[i] * 8;
    cpa16(s0 + qrow[i] * (APITCH * 2) + qch[i] * 16, src);
  }
  #pragma unroll
  for (int p = 0; p < 3; p++) {
    int kr0 = p * 64;
    #pragma unroll
    for (int i = 0; i < 2; i++) {
      const bf16* ks = Kg + ((size_t)(b * LJ + kr0 + crow[i])) * KVN + kvh * HD + cch[i] * 8;
      const bf16* vs = vbase + (size_t)crow[i] * LJ + kr0 + cch[i] * 8;
      cpa16(s0 + AKOFF(p) + crow[i] * (APITCH * 2) + cch[i] * 16, ks);
      cpa16(s0 + AVOFF(p) + crow[i] * (APITCH * 2) + cch[i] * 16, vs);
    }
    CPA_COMMIT;
  }

  float o[8][4];
  #pragma unroll
  for (int nt = 0; nt < 8; nt++)
    #pragma unroll
    for (int i = 0; i < 4; i++) o[nt][i] = 0.f;
  float mi0 = -1e30f, mi1 = -1e30f, li0 = 0.f, li1 = 0.f;

  uint32_t qf[4][4];
  int r0 = lane >> 2;
  int kc0 = 2 * (lane & 3);
  uint32_t q_ldm = (uint32_t)(wid * 16 + (lane & 15)) * (APITCH * 2) + ((lane >> 4) << 4);
  uint32_t kv_ldm = (uint32_t)(((lane >> 4) << 3) + (lane & 7)) * (APITCH * 2)
                    + (((lane >> 3) & 1) << 4);

  for (int it = 0; it < nT; it++) {
    CPA_WAIT2;
    __syncthreads();
    if (it + 3 < nT) {
      int st = (it + 3) & 3;
      int kr0 = (it + 3) * 64;
      #pragma unroll
      for (int i = 0; i < 2; i++) {
        const bf16* ks = Kg + ((size_t)(b * LJ + kr0 + crow[i])) * KVN + kvh * HD + cch[i] * 8;
        const bf16* vs = vbase + (size_t)crow[i] * LJ + kr0 + cch[i] * 8;
        cpa16(s0 + AKOFF(st) + crow[i] * (APITCH * 2) + cch[i] * 16, ks);
        cpa16(s0 + AVOFF(st) + crow[i] * (APITCH * 2) + cch[i] * 16, vs);
      }
    }
    CPA_COMMIT;

    if (it == 0) {
      #pragma unroll
      for (int kk = 0; kk < 4; kk++)
        ldmx4(qf[kk], s0 + q_ldm + kk * 32);
    }

    // ---- S = Q K^T ----
    uint32_t Kb = s0 + AKOFF(it & 3);
    float s[8][4];
    #pragma unroll
    for (int nt = 0; nt < 8; nt++)
      s[nt][0] = s[nt][1] = s[nt][2] = s[nt][3] = 0.f;
    #pragma unroll
    for (int kk = 0; kk < 4; kk++) {
      uint32_t kb4[4][4];
      #pragma unroll
      for (int j = 0; j < 4; j++)
        ldmx4(kb4[j], Kb + kv_ldm + (uint32_t)(j * 16) * (APITCH * 2) + kk * 32);
      #pragma unroll
      for (int j = 0; j < 4; j++) {
        mma_bf16(s[2 * j],     qf[kk], kb4[j][0], kb4[j][1]);
        mma_bf16(s[2 * j + 1], qf[kk], kb4[j][2], kb4[j][3]);
      }
    }

    // causal mask (expert q-block, last KV tile only)
    if (q0 >= LV && it == nT - 1) {
      int tk = it * 64;
      int rl = q0 + wid * 16 + r0;
      #pragma unroll
      for (int nt = 0; nt < 8; nt++) {
        int key = tk + nt * 8 + kc0;
        if (key > rl)         s[nt][0] = -1e30f;
        if (key + 1 > rl)     s[nt][1] = -1e30f;
        if (key > rl + 8)     s[nt][2] = -1e30f;
        if (key + 1 > rl + 8) s[nt][3] = -1e30f;
      }
    }

    // ---- online softmax; p overwrites s ----
    {
      float tm0 = -1e30f, tm1 = -1e30f;
      #pragma unroll
      for (int nt = 0; nt < 8; nt++) {
        tm0 = fmaxf(tm0, fmaxf(s[nt][0], s[nt][1]));
        tm1 = fmaxf(tm1, fmaxf(s[nt][2], s[nt][3]));
      }
      tm0 = fmaxf(tm0, __shfl_xor_sync(0xffffffffu, tm0, 1));
      tm0 = fmaxf(tm0, __shfl_xor_sync(0xffffffffu, tm0, 2));
      tm1 = fmaxf(tm1, __shfl_xor_sync(0xffffffffu, tm1, 1));
      tm1 = fmaxf(tm1, __shfl_xor_sync(0xffffffffu, tm1, 2));
      float mn0 = fmaxf(mi0, tm0), mn1 = fmaxf(mi1, tm1);
      float cr0 = ex2((mi0 - mn0) * CEXP), cr1 = ex2((mi1 - mn1) * CEXP);
      li0 *= cr0; li1 *= cr1;
      #pragma unroll
      for (int nt = 0; nt < 8; nt++) {
        o[nt][0] *= cr0; o[nt][1] *= cr0;
        o[nt][2] *= cr1; o[nt][3] *= cr1;
      }
      #pragma unroll
      for (int nt = 0; nt < 8; nt++) {
        float p0 = ex2((s[nt][0] - mn0) * CEXP);
        float p1 = ex2((s[nt][1] - mn0) * CEXP);
        float p2 = ex2((s[nt][2] - mn1) * CEXP);
        float p3 = ex2((s[nt][3] - mn1) * CEXP);
        li0 += p0 + p1;
        li1 += p2 + p3;
        s[nt][0] = p0; s[nt][1] = p1; s[nt][2] = p2; s[nt][3] = p3;
      }
      mi0 = mn0; mi1 = mn1;
    }

    // ---- O += P V (P direct from registers) ----
    uint32_t Vb = s0 + AVOFF(it & 3);
    #pragma unroll
    for (int kk = 0; kk < 4; kk++) {
      uint32_t a[4];
      a[0] = packbf(s[2 * kk][0], s[2 * kk][1]);
      a[1] = packbf(s[2 * kk][2], s[2 * kk][3]);
      a[2] = packbf(s[2 * kk + 1][0], s[2 * kk + 1][1]);
      a[3] = packbf(s[2 * kk + 1][2], s[2 * kk + 1][3]);
      uint32_t vb4[4][4];
      #pragma unroll
      for (int j = 0; j < 4; j++)
        ldmx4(vb4[j], Vb + kv_ldm + (uint32_t)(j * 16) * (APITCH * 2) + kk * 32);
      #pragma unroll
      for (int j = 0; j < 4; j++) {
        mma_bf16(o[2 * j],     a, vb4[j][0], vb4[j][1]);
        mma_bf16(o[2 * j + 1], a, vb4[j][2], vb4[j][3]);
      }
    }
  }

  // finalize
  if (q0 + wid * 16 < LJ) {
    float l0 = li0, l1 = li1;
    l0 += __shfl_xor_sync(0xffffffffu, l0, 1);
    l0 += __shfl_xor_sync(0xffffffffu, l0, 2);
    l1 += __shfl_xor_sync(0xffffffffu, l1, 1);
    l1 += __shfl_xor_sync(0xffffffffu, l1, 2);
    float inv0 = 1.f / l0, inv1 = 1.f / l1;
    int gr0 = b * LJ + q0 + wid * 16 + r0;
    #pragma unroll
    for (int nt = 0; nt < 8; nt++) {
      int cn = h * HD + nt * 8 + kc0;
      *(uint32_t*)(Og + (size_t)gr0 * QN + cn) = packbf(o[nt][0] * inv0, o[nt][1] * inv0);
      *(uint32_t*)(Og + (size_t)(gr0 + 8) * QN + cn) = packbf(o[nt][2] * inv1, o[nt][3] * inv1);
    }
  }
}

// ---------------------------------------------------------------------------
// Launch
// ---------------------------------------------------------------------------
extern "C" void kernel_launch(void* const* d_in, const int* in_sizes, int n_in,
                              void* d_out, int out_size) {
  const float* hv  = (const float*)d_in[0];
  const float* he  = (const float*)d_in[1];
  const float* lnv = (const float*)d_in[2];
  const float* wqv = (const float*)d_in[3];
  const float* wkv = (const float*)d_in[4];
  const float* wvv = (const float*)d_in[5];
  const float* wov = (const float*)d_in[6];
  const float* lne = (const float*)d_in[7];
  const float* wqe = (const float*)d_in[8];
  const float* wke = (const float*)d_in[9];
  const float* wve = (const float*)d_in[10];
  const float* woe = (const float*)d_in[11];
  const int* pv = (const int*)d_in[12];
  const int* pe = (const int*)d_in[13];
  float* out = (float*)d_out;

  bf16 *xhv, *xhe, *qh, *kh, *vt, *attn, *wh;
  cudaGetSymbolAddress((void**)&xhv, g_xh_v);
  cudaGetSymbolAddress((void**)&xhe, g_xh_e);
  cudaGetSymbolAddress((void**)&qh,  g_qh);
  cudaGetSymbolAddress((void**)&kh,  g_kh);
  cudaGetSymbolAddress((void**)&vt,  g_vt);
  cudaGetSymbolAddress((void**)&attn, g_attn);
  cudaGetSymbolAddress((void**)&wh,  g_wh);

  cudaFuncSetAttribute(gemm_bf16, cudaFuncAttributeMaxDynamicSharedMemorySize, GEMM_SMEM);
  cudaFuncSetAttribute(attn_mma, cudaFuncAttributeMaxDynamicSharedMemorySize, ATTN_SMEM);

  const int SQ = 960 * 960, SK = 960 * 320;
  bf16* cwqv = wh;
  bf16* cwkv = wh + SQ;
  bf16* cwvv = wh + SQ + SK;
  bf16* cwov = wh + SQ + 2 * SK;
  bf16* cwqe = wh + 2 * SQ + 2 * SK;
  bf16* cwke = wh + 3 * SQ + 2 * SK;
  bf16* cwve = wh + 3 * SQ + 3 * SK;
  bf16* cwoe = wh + 3 * SQ + 4 * SK;

  // 0) Fused weight transpose+convert (1 launch)
  WP8 wp;
  wp.src[0] = wqv; wp.src[1] = wkv; wp.src[2] = wvv; wp.src[3] = wov;
  wp.src[4] = wqe; wp.src[5] = wke; wp.src[6] = wve; wp.src[7] = woe;
  cvt_all<<<dim3(30, 30, 8), dim3(32, 8)>>>(wp, wh);

  // 1) RMSNorm (bf16 outputs)
  rmsnorm_kernel<<<NB * LV, 256>>>(hv, lnv, xhv);
  rmsnorm_kernel<<<NB * LE, 256>>>(he, lne, xhe);

  // 2) QKV projections
  gemm_bf16<<<dim3(QN / 64, 32), 512, GEMM_SMEM>>>(xhv, cwqv, nullptr, qh, nullptr, QN,  DMODEL, LV, 0,  0, 0);
  gemm_bf16<<<dim3(KVN / 64, 32), 512, GEMM_SMEM>>>(xhv, cwkv, nullptr, kh, nullptr, KVN, DMODEL, LV, 0,  0, 0);
  gemm_bf16<<<dim3(KVN / 64, 32), 512, GEMM_SMEM>>>(xhv, cwvv, nullptr, vt, nullptr, KVN, DMODEL, LV, 0,  0, 2);
  gemm_bf16<<<dim3(QN / 64, 1), 512, GEMM_SMEM>>>(xhe, cwqe, nullptr, qh, nullptr, QN,  DMODEL, LE, LV, 0, 0);
  gemm_bf16<<<dim3(KVN / 64, 1), 512, GEMM_SMEM>>>(xhe, cwke, nullptr, kh, nullptr, KVN, DMODEL, LE, LV, 0, 0);
  gemm_bf16<<<dim3(KVN / 64, 1), 512, GEMM_SMEM>>>(xhe, cwve, nullptr, vt, nullptr, KVN, DMODEL, LE, LV, 0, 2);

  // 3) RoPE on q and k (in place, bf16, fp32 math)
  int pq = NB * LJ * NH;
  int pk = NB * LJ * NKVH;
  rope_kernel<<<(pq + 7) / 8, 256>>>(qh, NH,   pq, pv, pe);
  rope_kernel<<<(pk + 7) / 8, 256>>>(kh, NKVH, pk, pv, pe);

  // 4) Attention (128 q rows per block, 8 warps, 2 CTAs/SM)
  attn_mma<<<dim3((LJ + 127) / 128, NH, NB), 256, ATTN_SMEM>>>(qh, kh, vt, attn);

  // 5) Output projection + residual
  gemm_bf16<<<dim3(QN / 64, 32), 512, GEMM_SMEM>>>(attn, cwov, out, nullptr, hv, QN, DMODEL, LV, 0,  1, 1);
  gemm_bf16<<<dim3(QN / 64, 1), 512, GEMM_SMEM>>>(attn, cwoe, out, nullptr, he, QN, DMODEL, LE, LV, 1, 1);
}